// round 6
// baseline (speedup 1.0000x reference)
#include <cuda_runtime.h>
#include <cuda_fp16.h>
#include <cstdint>

#define B_ 512
#define N_ 512
#define M_ 512
#define T_ 100

// Scratch (device globals — no allocation at kernel_launch time)
__device__ __half g_S[(size_t)B_ * T_ * N_];   // [b][t][n], values ±1, fp16 (52.4 MB)
__device__ __half g_W[(size_t)M_ * N_];        // fp16 copy of weight

// ---------------------------------------------------------------------------
// Threefry2x32-20 with key (0, 42)  — matches jax.random.key(42)
// ---------------------------------------------------------------------------
__device__ __forceinline__ uint32_t rotl32(uint32_t x, int d) {
    return __funnelshift_l(x, x, d);
}
__device__ __forceinline__ void tfround(uint32_t& x0, uint32_t& x1, int r) {
    x0 += x1; x1 = rotl32(x1, r); x1 ^= x0;
}
__device__ __forceinline__ void threefry(uint32_t& x0, uint32_t& x1) {
    const uint32_t k0 = 0u, k1 = 42u, k2 = 0x1BD11BF0u;  // 0x1BD11BDA ^ 0 ^ 42
    x0 += k0; x1 += k1;
    tfround(x0,x1,13); tfround(x0,x1,15); tfround(x0,x1,26); tfround(x0,x1, 6);
    x0 += k1; x1 += k2 + 1u;
    tfround(x0,x1,17); tfround(x0,x1,29); tfround(x0,x1,16); tfround(x0,x1,24);
    x0 += k2; x1 += k0 + 2u;
    tfround(x0,x1,13); tfround(x0,x1,15); tfround(x0,x1,26); tfround(x0,x1, 6);
    x0 += k0; x1 += k1 + 3u;
    tfround(x0,x1,17); tfround(x0,x1,29); tfround(x0,x1,16); tfround(x0,x1,24);
    x0 += k1; x1 += k2 + 4u;
    tfround(x0,x1,13); tfround(x0,x1,15); tfround(x0,x1,26); tfround(x0,x1, 6);
    x0 += k2; x1 += k0 + 5u;
}
__device__ __forceinline__ float u01(uint32_t bits) {
    return __uint_as_float((bits >> 9) | 0x3F800000u) - 1.0f;
}

// ---------------------------------------------------------------------------
// Sample generation — PARTITIONABLE threefry path (JAX >= 0.4.36 default):
// element i (flat index into [B,N,T]) uses its own block with 64-bit counter i:
//   (o0,o1) = threefry_{(0,42)}(hi32(i)=0, lo32(i)=i);  bits[i] = o0 ^ o1
// Thread = one (b, n); loops t = 0..99. i = (b*512+n)*100 + t.
// ---------------------------------------------------------------------------
__global__ void gen_kernel(const float* __restrict__ input) {
    int idx = blockIdx.x * blockDim.x + threadIdx.x;   // 0 .. 262143  = b*512+n
    int b = idx >> 9;
    int n = idx & 511;
    float p = 0.5f + 0.5f * input[idx];
    uint32_t jb = (uint32_t)idx * 100u;
    const __half POS = __float2half_rn(1.0f);
    const __half NEG = __float2half_rn(-1.0f);
    __half* sp = g_S + (size_t)b * T_ * N_ + n;
    #pragma unroll 4
    for (int t = 0; t < T_; t++) {
        uint32_t x0 = 0u;
        uint32_t x1 = jb + (uint32_t)t;
        threefry(x0, x1);
        uint32_t bits = x0 ^ x1;
        sp[(size_t)t * N_] = (u01(bits) < p) ? POS : NEG;
    }
}

__global__ void wconv_kernel(const float* __restrict__ W) {
    int i = blockIdx.x * blockDim.x + threadIdx.x;
    if (i < M_ * N_) g_W[i] = __float2half_rn(W[i]);
}

// ---------------------------------------------------------------------------
// Fused GEMM + erf + mean-over-t.
// Grid: (M/128, B). Block 256 threads = 8 warps (2 row-warps x 4 col-warps).
// C tile: 128 rows (t, padded; valid t<100) x 128 cols (m), K = 512.
// ---------------------------------------------------------------------------
#define SROW 24            // smem row stride in halfs (48B: conflict-free ldmatrix)
#define BUFB (128 * SROW * 2)  // bytes per buffer

__device__ __forceinline__ void ldmx4(uint32_t& r0, uint32_t& r1, uint32_t& r2, uint32_t& r3, uint32_t addr) {
    asm volatile("ldmatrix.sync.aligned.m8n8.x4.shared.b16 {%0,%1,%2,%3}, [%4];"
                 : "=r"(r0), "=r"(r1), "=r"(r2), "=r"(r3) : "r"(addr));
}
__device__ __forceinline__ void ldmx2(uint32_t& r0, uint32_t& r1, uint32_t addr) {
    asm volatile("ldmatrix.sync.aligned.m8n8.x2.shared.b16 {%0,%1}, [%2];"
                 : "=r"(r0), "=r"(r1) : "r"(addr));
}
__device__ __forceinline__ void mma16816(float* c, const uint32_t* a, const uint32_t* b) {
    asm volatile("mma.sync.aligned.m16n8k16.row.col.f32.f16.f16.f32 "
                 "{%0,%1,%2,%3}, {%4,%5,%6,%7}, {%8,%9}, {%0,%1,%2,%3};"
                 : "+f"(c[0]), "+f"(c[1]), "+f"(c[2]), "+f"(c[3])
                 : "r"(a[0]), "r"(a[1]), "r"(a[2]), "r"(a[3]), "r"(b[0]), "r"(b[1]));
}

__global__ void __launch_bounds__(256, 2)
gemm_kernel(const float* __restrict__ bias, float* __restrict__ out) {
    __shared__ __half As[2][128 * SROW];
    __shared__ __half Bs[2][128 * SROW];
    __shared__ float red[2][128];   // [wr][col] — fully written: wc partitions cols

    const int b     = blockIdx.y;
    const int mtile = blockIdx.x * 128;
    const int tid   = threadIdx.x;
    const int lane  = tid & 31;
    const int wid   = tid >> 5;
    const int wr    = wid >> 2;        // warp row (0..1): rows wr*64..wr*64+63
    const int wc    = wid & 3;         // warp col (0..3): cols wc*32..wc*32+31
    const int g     = lane >> 2;       // fragment row group
    const int tq    = lane & 3;        // fragment col pair

    // ---- global load mapping: one 16B A-load + one 16B B-load per thread ----
    const int lrow  = tid >> 1;          // 0..127
    const int lhalf = (tid & 1) * 8;     // 0 or 8 halfs
    const bool avalid = (lrow < T_);
    const __half* Aptr = g_S + (size_t)(b * T_ + lrow) * N_ + lhalf;   // only if avalid
    const __half* Bptr = g_W + (size_t)(mtile + lrow) * N_ + lhalf;

    // ---- accumulators initialized with bias ----
    float c[4][4][4];
    #pragma unroll
    for (int j = 0; j < 4; j++) {
        int col = mtile + wc * 32 + j * 8 + 2 * tq;
        float b0 = __ldg(bias + col);
        float b1 = __ldg(bias + col + 1);
        #pragma unroll
        for (int i = 0; i < 4; i++) {
            c[i][j][0] = b0; c[i][j][1] = b1; c[i][j][2] = b0; c[i][j][3] = b1;
        }
    }

    // ---- smem addresses ----
    uint32_t asb = (uint32_t)__cvta_generic_to_shared(&As[0][0]);
    uint32_t bsb = (uint32_t)__cvta_generic_to_shared(&Bs[0][0]);
    const int l16 = lane & 15;
    uint32_t aLd[4], bLd[4];
    #pragma unroll
    for (int i = 0; i < 4; i++)
        aLd[i] = asb + (uint32_t)(((wr * 64 + i * 16 + l16) * SROW + (lane >> 4) * 8) * 2);
    #pragma unroll
    for (int j = 0; j < 4; j++)
        bLd[j] = bsb + (uint32_t)(((wc * 32 + j * 8 + (l16 & 7)) * SROW + ((l16 >> 3) & 1) * 8) * 2);

    // ---- prologue: load k-tile 0 ----
    uint4 zero4 = make_uint4(0u, 0u, 0u, 0u);
    uint4 ra = avalid ? *(const uint4*)(Aptr) : zero4;
    uint4 rb = *(const uint4*)(Bptr);
    *(uint4*)(&As[0][lrow * SROW + lhalf]) = ra;
    *(uint4*)(&Bs[0][lrow * SROW + lhalf]) = rb;
    __syncthreads();

    // ---- main loop: K = 512, 32 steps of 16, double buffered ----
    #pragma unroll 1
    for (int ks = 0; ks < 32; ks++) {
        const int buf = ks & 1;
        if (ks < 31) {
            ra = avalid ? *(const uint4*)(Aptr + (ks + 1) * 16) : zero4;
            rb = *(const uint4*)(Bptr + (ks + 1) * 16);
        }
        uint32_t af[4][4], bf[4][2];
        #pragma unroll
        for (int i = 0; i < 4; i++)
            ldmx4(af[i][0], af[i][1], af[i][2], af[i][3], aLd[i] + buf * BUFB);
        #pragma unroll
        for (int j = 0; j < 4; j++)
            ldmx2(bf[j][0], bf[j][1], bLd[j] + buf * BUFB);
        #pragma unroll
        for (int i = 0; i < 4; i++) {
            // rows for (wr==1, i==3) are 112..127: all zero padding (T=100) — skip
            if (wr == 0 || i < 3) {
                #pragma unroll
                for (int j = 0; j < 4; j++)
                    mma16816(c[i][j], af[i], bf[j]);
            }
        }
        if (ks < 31) {
            __syncthreads();
            *(uint4*)(&As[buf ^ 1][lrow * SROW + lhalf]) = ra;
            *(uint4*)(&Bs[buf ^ 1][lrow * SROW + lhalf]) = rb;
            __syncthreads();
        }
    }

    // ---- epilogue: erf, mask invalid t rows, reduce over t, mean ----
    const float ZS = 0.03125f;  // 1/sqrt(2*512)
    #pragma unroll
    for (int j = 0; j < 4; j++) {
        float s0 = 0.0f, s1 = 0.0f;
        #pragma unroll
        for (int i = 0; i < 4; i++) {
            int r0 = wr * 64 + i * 16 + g;
            int r1 = r0 + 8;
            if (r0 < T_) { s0 += erff(c[i][j][0] * ZS); s1 += erff(c[i][j][1] * ZS); }
            if (r1 < T_) { s0 += erff(c[i][j][2] * ZS); s1 += erff(c[i][j][3] * ZS); }
        }
        #pragma unroll
        for (int off = 16; off >= 4; off >>= 1) {
            s0 += __shfl_down_sync(0xffffffffu, s0, off);
            s1 += __shfl_down_sync(0xffffffffu, s1, off);
        }
        if (lane < 4) {
            int colL = wc * 32 + j * 8 + 2 * tq;
            red[wr][colL]     = s0;
            red[wr][colL + 1] = s1;
        }
    }
    __syncthreads();
    if (tid < 128) {
        float acc = red[0][tid] + red[1][tid];
        out[(size_t)b * M_ + mtile + tid] = acc * 0.01f;   // mean over T=100
    }
}

// ---------------------------------------------------------------------------
extern "C" void kernel_launch(void* const* d_in, const int* in_sizes, int n_in,
                              void* d_out, int out_size) {
    const float* input  = (const float*)d_in[0];   // [512, 512]
    const float* weight = (const float*)d_in[1];   // [512, 512]
    const float* bias   = (const float*)d_in[2];   // [512]
    float* out = (float*)d_out;                    // [512, 512]

    gen_kernel<<<1024, 256>>>(input);
    wconv_kernel<<<512, 512>>>(weight);
    gemm_kernel<<<dim3(4, 512), 256>>>(bias, out);
}

// round 7
// speedup vs baseline: 1.0009x; 1.0009x over previous
#include <cuda_runtime.h>
#include <cuda_fp16.h>
#include <cstdint>

#define B_ 512
#define N_ 512
#define M_ 512
#define T_ 100

// Scratch (device globals — no allocation at kernel_launch time)
__device__ __half g_S[(size_t)B_ * T_ * N_];   // [b][t][n], values ±1, fp16 (52.4 MB)
__device__ __half g_W[(size_t)M_ * N_];        // fp16 copy of weight

// ---------------------------------------------------------------------------
// Threefry2x32-20 with key (0, 42)  — matches jax.random.key(42)
// ---------------------------------------------------------------------------
__device__ __forceinline__ uint32_t rotl32(uint32_t x, int d) {
    return __funnelshift_l(x, x, d);
}
__device__ __forceinline__ void tfround(uint32_t& x0, uint32_t& x1, int r) {
    x0 += x1; x1 = rotl32(x1, r); x1 ^= x0;
}
__device__ __forceinline__ void threefry(uint32_t& x0, uint32_t& x1) {
    const uint32_t k0 = 0u, k1 = 42u, k2 = 0x1BD11BF0u;  // 0x1BD11BDA ^ 0 ^ 42
    x0 += k0; x1 += k1;
    tfround(x0,x1,13); tfround(x0,x1,15); tfround(x0,x1,26); tfround(x0,x1, 6);
    x0 += k1; x1 += k2 + 1u;
    tfround(x0,x1,17); tfround(x0,x1,29); tfround(x0,x1,16); tfround(x0,x1,24);
    x0 += k2; x1 += k0 + 2u;
    tfround(x0,x1,13); tfround(x0,x1,15); tfround(x0,x1,26); tfround(x0,x1, 6);
    x0 += k0; x1 += k1 + 3u;
    tfround(x0,x1,17); tfround(x0,x1,29); tfround(x0,x1,16); tfround(x0,x1,24);
    x0 += k1; x1 += k2 + 4u;
    tfround(x0,x1,13); tfround(x0,x1,15); tfround(x0,x1,26); tfround(x0,x1, 6);
    x0 += k2; x1 += k0 + 5u;
}
__device__ __forceinline__ float u01(uint32_t bits) {
    return __uint_as_float((bits >> 9) | 0x3F800000u) - 1.0f;
}

// ---------------------------------------------------------------------------
// Sample generation — PARTITIONABLE threefry path (JAX >= 0.4.36 default):
// element i (flat index into [B,N,T]) uses its own block with 64-bit counter i:
//   (o0,o1) = threefry_{(0,42)}(hi32(i)=0, lo32(i)=i);  bits[i] = o0 ^ o1
// Thread = one (b, n); loops t = 0..99. i = (b*512+n)*100 + t.
// ---------------------------------------------------------------------------
__global__ void gen_kernel(const float* __restrict__ input) {
    int idx = blockIdx.x * blockDim.x + threadIdx.x;   // 0 .. 262143  = b*512+n
    int b = idx >> 9;
    int n = idx & 511;
    float p = 0.5f + 0.5f * input[idx];
    uint32_t jb = (uint32_t)idx * 100u;
    const __half POS = __float2half_rn(1.0f);
    const __half NEG = __float2half_rn(-1.0f);
    __half* sp = g_S + (size_t)b * T_ * N_ + n;
    #pragma unroll 4
    for (int t = 0; t < T_; t++) {
        uint32_t x0 = 0u;
        uint32_t x1 = jb + (uint32_t)t;
        threefry(x0, x1);
        uint32_t bits = x0 ^ x1;
        sp[(size_t)t * N_] = (u01(bits) < p) ? POS : NEG;
    }
}

__global__ void wconv_kernel(const float* __restrict__ W) {
    int i = blockIdx.x * blockDim.x + threadIdx.x;
    if (i < M_ * N_) g_W[i] = __float2half_rn(W[i]);
}

// ---------------------------------------------------------------------------
// Fused GEMM + erf + mean-over-t.
// Grid: (M/128, B). Block 256 threads = 8 warps (2 row-warps x 4 col-warps).
// C tile: 128 rows (t, padded; valid t<100) x 128 cols (m), K = 512.
// ---------------------------------------------------------------------------
#define SROW 24            // smem row stride in halfs (48B: conflict-free ldmatrix)
#define BUFB (128 * SROW * 2)  // bytes per buffer

__device__ __forceinline__ void ldmx4(uint32_t& r0, uint32_t& r1, uint32_t& r2, uint32_t& r3, uint32_t addr) {
    asm volatile("ldmatrix.sync.aligned.m8n8.x4.shared.b16 {%0,%1,%2,%3}, [%4];"
                 : "=r"(r0), "=r"(r1), "=r"(r2), "=r"(r3) : "r"(addr));
}
__device__ __forceinline__ void ldmx2(uint32_t& r0, uint32_t& r1, uint32_t addr) {
    asm volatile("ldmatrix.sync.aligned.m8n8.x2.shared.b16 {%0,%1}, [%2];"
                 : "=r"(r0), "=r"(r1) : "r"(addr));
}
__device__ __forceinline__ void mma16816(float* c, const uint32_t* a, const uint32_t* b) {
    asm volatile("mma.sync.aligned.m16n8k16.row.col.f32.f16.f16.f32 "
                 "{%0,%1,%2,%3}, {%4,%5,%6,%7}, {%8,%9}, {%0,%1,%2,%3};"
                 : "+f"(c[0]), "+f"(c[1]), "+f"(c[2]), "+f"(c[3])
                 : "r"(a[0]), "r"(a[1]), "r"(a[2]), "r"(a[3]), "r"(b[0]), "r"(b[1]));
}

__global__ void __launch_bounds__(256, 2)
gemm_kernel(const float* __restrict__ bias, float* __restrict__ out) {
    __shared__ __half As[2][128 * SROW];
    __shared__ __half Bs[2][128 * SROW];
    __shared__ float red[2][128];   // [wr][col] — fully written: wc partitions cols

    const int b     = blockIdx.y;
    const int mtile = blockIdx.x * 128;
    const int tid   = threadIdx.x;
    const int lane  = tid & 31;
    const int wid   = tid >> 5;
    const int wr    = wid >> 2;        // warp row (0..1): rows wr*64..wr*64+63
    const int wc    = wid & 3;         // warp col (0..3): cols wc*32..wc*32+31
    const int g     = lane >> 2;       // fragment row group
    const int tq    = lane & 3;        // fragment col pair

    // ---- global load mapping: one 16B A-load + one 16B B-load per thread ----
    const int lrow  = tid >> 1;          // 0..127
    const int lhalf = (tid & 1) * 8;     // 0 or 8 halfs
    const bool avalid = (lrow < T_);
    const __half* Aptr = g_S + (size_t)(b * T_ + lrow) * N_ + lhalf;   // only if avalid
    const __half* Bptr = g_W + (size_t)(mtile + lrow) * N_ + lhalf;

    // ---- accumulators initialized with bias ----
    float c[4][4][4];
    #pragma unroll
    for (int j = 0; j < 4; j++) {
        int col = mtile + wc * 32 + j * 8 + 2 * tq;
        float b0 = __ldg(bias + col);
        float b1 = __ldg(bias + col + 1);
        #pragma unroll
        for (int i = 0; i < 4; i++) {
            c[i][j][0] = b0; c[i][j][1] = b1; c[i][j][2] = b0; c[i][j][3] = b1;
        }
    }

    // ---- smem addresses ----
    uint32_t asb = (uint32_t)__cvta_generic_to_shared(&As[0][0]);
    uint32_t bsb = (uint32_t)__cvta_generic_to_shared(&Bs[0][0]);
    const int l16 = lane & 15;
    uint32_t aLd[4], bLd[4];
    #pragma unroll
    for (int i = 0; i < 4; i++)
        aLd[i] = asb + (uint32_t)(((wr * 64 + i * 16 + l16) * SROW + (lane >> 4) * 8) * 2);
    #pragma unroll
    for (int j = 0; j < 4; j++)
        bLd[j] = bsb + (uint32_t)(((wc * 32 + j * 8 + (l16 & 7)) * SROW + ((l16 >> 3) & 1) * 8) * 2);

    // ---- prologue: load k-tile 0 ----
    uint4 zero4 = make_uint4(0u, 0u, 0u, 0u);
    uint4 ra = avalid ? *(const uint4*)(Aptr) : zero4;
    uint4 rb = *(const uint4*)(Bptr);
    *(uint4*)(&As[0][lrow * SROW + lhalf]) = ra;
    *(uint4*)(&Bs[0][lrow * SROW + lhalf]) = rb;
    __syncthreads();

    // ---- main loop: K = 512, 32 steps of 16, double buffered ----
    #pragma unroll 1
    for (int ks = 0; ks < 32; ks++) {
        const int buf = ks & 1;
        if (ks < 31) {
            ra = avalid ? *(const uint4*)(Aptr + (ks + 1) * 16) : zero4;
            rb = *(const uint4*)(Bptr + (ks + 1) * 16);
        }
        uint32_t af[4][4], bf[4][2];
        #pragma unroll
        for (int i = 0; i < 4; i++)
            ldmx4(af[i][0], af[i][1], af[i][2], af[i][3], aLd[i] + buf * BUFB);
        #pragma unroll
        for (int j = 0; j < 4; j++)
            ldmx2(bf[j][0], bf[j][1], bLd[j] + buf * BUFB);
        #pragma unroll
        for (int i = 0; i < 4; i++) {
            // rows for (wr==1, i==3) are 112..127: all zero padding (T=100) — skip
            if (wr == 0 || i < 3) {
                #pragma unroll
                for (int j = 0; j < 4; j++)
                    mma16816(c[i][j], af[i], bf[j]);
            }
        }
        if (ks < 31) {
            __syncthreads();
            *(uint4*)(&As[buf ^ 1][lrow * SROW + lhalf]) = ra;
            *(uint4*)(&Bs[buf ^ 1][lrow * SROW + lhalf]) = rb;
            __syncthreads();
        }
    }

    // ---- epilogue: erf, mask invalid t rows, reduce over t, mean ----
    const float ZS = 0.03125f;  // 1/sqrt(2*512)
    #pragma unroll
    for (int j = 0; j < 4; j++) {
        float s0 = 0.0f, s1 = 0.0f;
        #pragma unroll
        for (int i = 0; i < 4; i++) {
            int r0 = wr * 64 + i * 16 + g;
            int r1 = r0 + 8;
            if (r0 < T_) { s0 += erff(c[i][j][0] * ZS); s1 += erff(c[i][j][1] * ZS); }
            if (r1 < T_) { s0 += erff(c[i][j][2] * ZS); s1 += erff(c[i][j][3] * ZS); }
        }
        #pragma unroll
        for (int off = 16; off >= 4; off >>= 1) {
            s0 += __shfl_down_sync(0xffffffffu, s0, off);
            s1 += __shfl_down_sync(0xffffffffu, s1, off);
        }
        if (lane < 4) {
            int colL = wc * 32 + j * 8 + 2 * tq;
            red[wr][colL]     = s0;
            red[wr][colL + 1] = s1;
        }
    }
    __syncthreads();
    if (tid < 128) {
        float acc = red[0][tid] + red[1][tid];
        out[(size_t)b * M_ + mtile + tid] = acc * 0.01f;   // mean over T=100
    }
}

// ---------------------------------------------------------------------------
extern "C" void kernel_launch(void* const* d_in, const int* in_sizes, int n_in,
                              void* d_out, int out_size) {
    const float* input  = (const float*)d_in[0];   // [512, 512]
    const float* weight = (const float*)d_in[1];   // [512, 512]
    const float* bias   = (const float*)d_in[2];   // [512]
    float* out = (float*)d_out;                    // [512, 512]

    gen_kernel<<<1024, 256>>>(input);
    wconv_kernel<<<512, 512>>>(weight);
    gemm_kernel<<<dim3(4, 512), 256>>>(bias, out);
}

// round 10
// speedup vs baseline: 1.2970x; 1.2958x over previous
#include <cuda_runtime.h>
#include <cuda_fp16.h>
#include <cstdint>

#define B_ 512
#define N_ 512
#define M_ 512
#define T_ 100

// Scratch (device globals — no allocation at kernel_launch time)
__device__ __half g_S[(size_t)B_ * T_ * N_];   // [b][t][n], values ±1, fp16 (52.4 MB)
__device__ __half g_W[(size_t)M_ * N_];        // fp16 copy of weight

// ===========================================================================
// Threefry2x32-20, key (0,42), partitionable path: bits = o0 ^ o1, ctr=(0, i)
// Adds routed to IMAD (fma pipe) via runtime 'one' so ptxas can't fold.
// ===========================================================================
__device__ __forceinline__ uint32_t rotl32(uint32_t x, int d) {
    return __funnelshift_l(x, x, d);
}
__device__ __forceinline__ uint32_t addi(uint32_t a, uint32_t b, uint32_t one) {
    uint32_t r;
    asm("mad.lo.u32 %0, %1, %2, %3;" : "=r"(r) : "r"(a), "r"(one), "r"(b));
    return r;
}
#define TFR(r) { x0 = addi(x0, x1, one); x1 = rotl32(x1, r); x1 ^= x0; }
__device__ __forceinline__ uint32_t tf_bits(uint32_t ctr, uint32_t one) {
    const uint32_t k1 = 42u, k2 = 0x1BD11BF0u;   // 0x1BD11BDA ^ 0 ^ 42
    uint32_t x1 = ctr + k1;       // x0+=k0(0); x1+=k1
    uint32_t x0 = x1;             // round 1: x0 = 0 + x1
    x1 = rotl32(x1, 13); x1 ^= x0;
    TFR(15) TFR(26) TFR(6)
    x0 = addi(x0, k1, one); x1 = addi(x1, k2 + 1u, one);
    TFR(17) TFR(29) TFR(16) TFR(24)
    x0 = addi(x0, k2, one); x1 = addi(x1, 0u + 2u, one);
    TFR(13) TFR(15) TFR(26) TFR(6)
    /* x0 += k0 (0) */              x1 = addi(x1, k1 + 3u, one);
    TFR(17) TFR(29) TFR(16) TFR(24)
    x0 = addi(x0, k1, one); x1 = addi(x1, k2 + 4u, one);
    TFR(13) TFR(15) TFR(26) TFR(6)
    x0 = addi(x0, k2, one); x1 = addi(x1, 0u + 5u, one);
    return x0 ^ x1;
}

// ---------------------------------------------------------------------------
// Sample generation. Integer Bernoulli threshold: u01(bits) < p  <=>
// (bits>>9) < ceil(p * 2^23)   (exact for p in [0.5, 1])
// ---------------------------------------------------------------------------
__global__ void gen_kernel(const float* __restrict__ input, uint32_t one) {
    int idx = blockIdx.x * blockDim.x + threadIdx.x;   // b*512+n
    int b = idx >> 9;
    int n = idx & 511;
    float p = 0.5f + 0.5f * input[idx];
    uint32_t mu = (uint32_t)ceilf(p * 8388608.0f);
    uint32_t jb = (uint32_t)idx * 100u;
    const __half POS = __float2half_rn(1.0f);
    const __half NEG = __float2half_rn(-1.0f);
    __half* sp = g_S + (size_t)b * T_ * N_ + n;
    #pragma unroll 4
    for (int t = 0; t < T_; t++) {
        uint32_t bits = tf_bits(jb + (uint32_t)t, one);
        sp[(size_t)t * N_] = ((bits >> 9) < mu) ? POS : NEG;
    }
}

__global__ void wconv_kernel(const float* __restrict__ W) {
    int i = blockIdx.x * blockDim.x + threadIdx.x;
    if (i < M_ * N_) g_W[i] = __float2half_rn(W[i]);
}

// ===========================================================================
// Fused GEMM + erf + mean-over-t  (mma.sync + cp.async 3-stage pipeline).
// Grid: (M/128, B). Block 256 threads = 8 warps (2 row-warps x 4 col-warps).
// C tile: 128 rows (t, padded) x 128 cols (m). K = 512 in 8 chunks of 64.
// smem: 3 stages x (A 16KB + B 16KB), SW128-swizzled 128B rows.
// ===========================================================================
#define SMEM_SWZ(off) ((off) ^ (((off) >> 3) & 0x70))
#define STAGEB 32768
#define NSTAGE 3
#define NCHUNK 8
#define SMEM_GEMM (NSTAGE * STAGEB)   // 98304 B

__device__ __forceinline__ uint32_t smem_u32(const void* p) {
    uint32_t a;
    asm("{ .reg .u64 t; cvta.to.shared.u64 t, %1; cvt.u32.u64 %0, t; }" : "=r"(a) : "l"(p));
    return a;
}
__device__ __forceinline__ void cpasync16(uint32_t dst, const void* src, uint32_t srcsize) {
    asm volatile("cp.async.cg.shared.global [%0], [%1], 16, %2;"
                 :: "r"(dst), "l"(src), "r"(srcsize) : "memory");
}
__device__ __forceinline__ void cpcommit() {
    asm volatile("cp.async.commit_group;" ::: "memory");
}
template <int NPending>
__device__ __forceinline__ void cpwait() {
    asm volatile("cp.async.wait_group %0;" :: "n"(NPending) : "memory");
}
__device__ __forceinline__ void ldmx4(uint32_t& r0, uint32_t& r1, uint32_t& r2, uint32_t& r3, uint32_t addr) {
    asm volatile("ldmatrix.sync.aligned.m8n8.x4.shared.b16 {%0,%1,%2,%3}, [%4];"
                 : "=r"(r0), "=r"(r1), "=r"(r2), "=r"(r3) : "r"(addr));
}
__device__ __forceinline__ void ldmx2(uint32_t& r0, uint32_t& r1, uint32_t addr) {
    asm volatile("ldmatrix.sync.aligned.m8n8.x2.shared.b16 {%0,%1}, [%2];"
                 : "=r"(r0), "=r"(r1) : "r"(addr));
}
__device__ __forceinline__ void mma16816(float* c, const uint32_t* a, const uint32_t* b) {
    asm volatile("mma.sync.aligned.m16n8k16.row.col.f32.f16.f16.f32 "
                 "{%0,%1,%2,%3}, {%4,%5,%6,%7}, {%8,%9}, {%0,%1,%2,%3};"
                 : "+f"(c[0]), "+f"(c[1]), "+f"(c[2]), "+f"(c[3])
                 : "r"(a[0]), "r"(a[1]), "r"(a[2]), "r"(a[3]), "r"(b[0]), "r"(b[1]));
}

__global__ void __launch_bounds__(256, 2)
gemm_kernel(const float* __restrict__ bias, float* __restrict__ out) {
    extern __shared__ char smem[];
    const uint32_t sbase = smem_u32(smem);

    const int b     = blockIdx.y;
    const int mtile = blockIdx.x * 128;
    const int tid   = threadIdx.x;
    const int lane  = tid & 31;
    const int wid   = tid >> 5;
    const int wr    = wid >> 2;        // warp row (0..1)
    const int wc    = wid & 3;         // warp col (0..3)
    const int g     = lane >> 2;
    const int tq    = lane & 3;

    const __half* Ab = g_S + (size_t)b * T_ * N_;
    const __half* Bb = g_W + (size_t)mtile * N_;

    // ---- per-thread cp.async mapping: 4 A-groups + 4 B-groups per chunk ----
    int ldRow[4], ldKg[4];
    uint32_t ldDst[4];
    #pragma unroll
    for (int i = 0; i < 4; i++) {
        int id = tid + i * 256;
        ldRow[i] = id >> 3;
        ldKg[i]  = id & 7;
        ldDst[i] = (uint32_t)SMEM_SWZ(ldRow[i] * 128 + ldKg[i] * 16);
    }

    // ---- accumulators initialized with bias ----
    float c[4][4][4];
    #pragma unroll
    for (int j = 0; j < 4; j++) {
        int col = mtile + wc * 32 + j * 8 + 2 * tq;
        float b0 = __ldg(bias + col);
        float b1 = __ldg(bias + col + 1);
        #pragma unroll
        for (int i = 0; i < 4; i++) {
            c[i][j][0] = b0; c[i][j][1] = b1; c[i][j][2] = b0; c[i][j][3] = b1;
        }
    }

    // ---- ldmatrix addressing: keep PRE-swizzle base ub and the per-fragment
    //      XOR mask x = (ub>>3)&0x70 (bits 7-9 = row, unchanged by +k*32).
    //      Per-k address = (ub + k*32) ^ x  — the R9 bug was (ub^x) + k*32. ----
    const int l16 = lane & 15;
    uint32_t aUb[4], aXm[4], bUb[4], bXm[4];
    #pragma unroll
    for (int i = 0; i < 4; i++) {
        uint32_t ub = (uint32_t)((wr * 64 + i * 16 + l16) * 128 + (lane >> 4) * 16);
        aUb[i] = ub; aXm[i] = (ub >> 3) & 0x70;
    }
    #pragma unroll
    for (int j = 0; j < 4; j++) {
        uint32_t ub = (uint32_t)((wc * 32 + j * 8 + (l16 & 7)) * 128 + ((l16 >> 3) & 1) * 16);
        bUb[j] = ub; bXm[j] = (ub >> 3) & 0x70;
    }

    // ---- stage loader ----
    auto load_chunk = [&](int chunk, int stage) {
        const uint32_t so = sbase + stage * STAGEB;
        #pragma unroll
        for (int i = 0; i < 4; i++) {          // A
            int row = ldRow[i];
            int rc = (row < T_) ? row : 0;     // clamp (src stays in-bounds)
            cpasync16(so + ldDst[i],
                      Ab + (size_t)rc * N_ + chunk * 64 + ldKg[i] * 8,
                      (row < T_) ? 16u : 0u);  // srcsize 0 -> zero-fill
        }
        #pragma unroll
        for (int i = 0; i < 4; i++) {          // B
            cpasync16(so + 16384 + ldDst[i],
                      Bb + (size_t)ldRow[i] * N_ + chunk * 64 + ldKg[i] * 8,
                      16u);
        }
        cpcommit();
    };

    // ---- compute one 64-K chunk from a given stage ----
    auto compute_chunk = [&](int stage) {
        const uint32_t soff = sbase + (uint32_t)(stage * STAGEB);
        #pragma unroll
        for (int k = 0; k < 4; k++) {
            const uint32_t ko = (uint32_t)(k * 32);
            uint32_t af[4][4], bf[4][2];
            #pragma unroll
            for (int i = 0; i < 4; i++)
                ldmx4(af[i][0], af[i][1], af[i][2], af[i][3],
                      soff + ((aUb[i] + ko) ^ aXm[i]));
            #pragma unroll
            for (int j = 0; j < 4; j++)
                ldmx2(bf[j][0], bf[j][1],
                      soff + 16384 + ((bUb[j] + ko) ^ bXm[j]));
            #pragma unroll
            for (int i = 0; i < 4; i++) {
                // rows for (wr==1, i==3) are 112..127: all zero padding — skip
                if (wr == 0 || i < 3) {
                    #pragma unroll
                    for (int j = 0; j < 4; j++)
                        mma16816(c[i][j], af[i], bf[j]);
                }
            }
        }
    };

    // ---- prologue: prefetch chunks 0,1 ----
    load_chunk(0, 0);
    load_chunk(1, 1);

    // ---- main loop: chunks 0..6 with <=1 group pending; chunk 7 with 0 ----
    #pragma unroll 1
    for (int ck = 0; ck < NCHUNK - 1; ck++) {
        cpwait<1>();                       // chunk ck resident
        __syncthreads();                   // all warps done with stage being reloaded
        if (ck + 2 < NCHUNK) load_chunk(ck + 2, (ck + 2) % NSTAGE);
        compute_chunk(ck % NSTAGE);
    }
    cpwait<0>();                           // final chunk fully resident
    __syncthreads();
    compute_chunk((NCHUNK - 1) % NSTAGE);
    __syncthreads();                       // before overlaying stage 0 with 'red'

    // ---- epilogue: erf, mask invalid t rows, reduce over t, mean ----
    float* red = (float*)smem;             // [2][128] overlay on stage 0
    const float ZS = 0.03125f;             // 1/sqrt(2*512)
    #pragma unroll
    for (int j = 0; j < 4; j++) {
        float s0 = 0.0f, s1 = 0.0f;
        #pragma unroll
        for (int i = 0; i < 4; i++) {
            int r0 = wr * 64 + i * 16 + g;
            int r1 = r0 + 8;
            if (r0 < T_) { s0 += erff(c[i][j][0] * ZS); s1 += erff(c[i][j][1] * ZS); }
            if (r1 < T_) { s0 += erff(c[i][j][2] * ZS); s1 += erff(c[i][j][3] * ZS); }
        }
        #pragma unroll
        for (int off = 16; off >= 4; off >>= 1) {
            s0 += __shfl_down_sync(0xffffffffu, s0, off);
            s1 += __shfl_down_sync(0xffffffffu, s1, off);
        }
        if (lane < 4) {
            int colL = wc * 32 + j * 8 + 2 * tq;
            red[wr * 128 + colL]     = s0;
            red[wr * 128 + colL + 1] = s1;
        }
    }
    __syncthreads();
    if (tid < 128) {
        float acc = red[tid] + red[128 + tid];
        out[(size_t)b * M_ + mtile + tid] = acc * 0.01f;   // mean over T=100
    }
}

// ---------------------------------------------------------------------------
extern "C" void kernel_launch(void* const* d_in, const int* in_sizes, int n_in,
                              void* d_out, int out_size) {
    const float* input  = (const float*)d_in[0];   // [512, 512]
    const float* weight = (const float*)d_in[1];   // [512, 512]
    const float* bias   = (const float*)d_in[2];   // [512]
    float* out = (float*)d_out;                    // [512, 512]

    cudaFuncSetAttribute(gemm_kernel, cudaFuncAttributeMaxDynamicSharedMemorySize, SMEM_GEMM);

    gen_kernel<<<1024, 256>>>(input, 1u);
    wconv_kernel<<<512, 512>>>(weight);
    gemm_kernel<<<dim3(4, 512), 256, SMEM_GEMM>>>(bias, out);
}